// round 12
// baseline (speedup 1.0000x reference)
#include <cuda_runtime.h>
#include <cuda_fp16.h>
#include <cstdint>
#include <math.h>

#define BB 4
#define NN 2048
#define CC 1024
#define N3 (3 * CC)
#define HH 16
#define HD 64
#define LT 256
#define NQ (NN - LT)        // 1792
#define MROWS (BB * NN)     // 8192
#define NT (NN / 64)        // 32 K-tiles
#define PLANE ((size_t)BB * HH * NN * HD)

__device__ __half g_qkvh[(size_t)3 * BB * HH * NN * HD];   // q,k,v planes fp16
__device__ __half g_vt[(size_t)BB * HH * HD * NN];         // V transposed [bh][d][n]
__device__ __half g_xs[(size_t)BB * NQ * CC];              // attention out fp16
__device__ __half g_xh[(size_t)MROWS * CC];                // x fp16
__device__ __half g_wh[(size_t)N3 * CC];                   // qkv_w fp16 [n][k]
__device__ __half g_ph[(size_t)CC * CC];                   // proj_w fp16 [n][k]

__device__ __forceinline__ uint32_t smem_u32(const void* p) {
    uint32_t a;
    asm("{ .reg .u64 t; cvta.to.shared.u64 t, %1; cvt.u32.u64 %0, t; }" : "=r"(a) : "l"(p));
    return a;
}
__device__ __forceinline__ void mma16(float* c,
                                      unsigned a0, unsigned a1, unsigned a2, unsigned a3,
                                      unsigned b0, unsigned b1) {
    asm volatile(
        "mma.sync.aligned.m16n8k16.row.col.f32.f16.f16.f32 "
        "{%0,%1,%2,%3},{%4,%5,%6,%7},{%8,%9},{%0,%1,%2,%3};"
        : "+f"(c[0]), "+f"(c[1]), "+f"(c[2]), "+f"(c[3])
        : "r"(a0), "r"(a1), "r"(a2), "r"(a3), "r"(b0), "r"(b1));
}
__device__ __forceinline__ void ldsm4(unsigned& r0, unsigned& r1, unsigned& r2, unsigned& r3,
                                      uint32_t addr) {
    asm volatile("ldmatrix.sync.aligned.m8n8.x4.shared.b16 {%0,%1,%2,%3}, [%4];"
                 : "=r"(r0), "=r"(r1), "=r"(r2), "=r"(r3) : "r"(addr));
}
__device__ __forceinline__ unsigned pack_h2(float a, float b) {
    __half2 h = __floats2half2_rn(a, b);
    return *(unsigned*)&h;
}
__device__ __forceinline__ unsigned ex2h2(unsigned x) {
    unsigned r;
    asm("ex2.approx.f16x2 %0, %1;" : "=r"(r) : "r"(x));
    return r;
}

#define CP_A16(dst, src) asm volatile("cp.async.cg.shared.global [%0], [%1], 16;" :: "r"(dst), "l"(src))
#define CP_COMMIT()      asm volatile("cp.async.commit_group;" ::: "memory")
#define CP_WAIT0()       asm volatile("cp.async.wait_group 0;" ::: "memory")
#define CP_WAIT1()       asm volatile("cp.async.wait_group 1;" ::: "memory")
#define CP_WAIT2()       asm volatile("cp.async.wait_group 2;" ::: "memory")

// 0.125 * log2(e): folded into Q at QKV epilogue so softmax = ex2(S)
#define QSCALE 0.1803368801111204f

// ---------------- fp32 -> fp16 converts ----------------
__global__ void convert_x_kernel(const float* __restrict__ x) {
    size_t i = ((size_t)blockIdx.x * 256 + threadIdx.x) * 8;
    float4 v0 = *(const float4*)(x + i);
    float4 v1 = *(const float4*)(x + i + 4);
    uint4 u;
    u.x = pack_h2(v0.x, v0.y);
    u.y = pack_h2(v0.z, v0.w);
    u.z = pack_h2(v1.x, v1.y);
    u.w = pack_h2(v1.z, v1.w);
    *(uint4*)&g_xh[i] = u;
}
__global__ void convert_w_kernel(const float* __restrict__ src, int which) {
    __half* dst = which ? g_ph : g_wh;
    size_t i = ((size_t)blockIdx.x * 256 + threadIdx.x) * 8;
    float4 v0 = *(const float4*)(src + i);
    float4 v1 = *(const float4*)(src + i + 4);
    uint4 u;
    u.x = pack_h2(v0.x, v0.y);
    u.y = pack_h2(v0.z, v0.w);
    u.z = pack_h2(v1.x, v1.y);
    u.w = pack_h2(v1.z, v1.w);
    *(uint4*)&dst[i] = u;
}

// ---------------- V plane transpose: [n][d] -> g_vt [d][n] ----------------
__global__ void vtrans_kernel() {
    __shared__ __half ts[64][72];
    const int bx = blockIdx.x, bh = blockIdx.y, tid = threadIdx.x;
    const __half* src = g_qkvh + 2 * PLANE + (size_t)bh * NN * HD + (size_t)bx * 64 * HD;
    {
        int n = tid >> 2, d0 = (tid & 3) * 16;
        *(uint4*)&ts[n][d0] = *(const uint4*)(src + (size_t)n * HD + d0);
        *(uint4*)&ts[n][d0 + 8] = *(const uint4*)(src + (size_t)n * HD + d0 + 8);
    }
    __syncthreads();
    {
        int d = tid >> 2, nb = (tid & 3) * 16;
        __half* dst = g_vt + (size_t)bh * HD * NN + (size_t)d * NN + bx * 64 + nb;
#pragma unroll
        for (int j = 0; j < 8; ++j) {
            unsigned v = pack_h2(__half2float(ts[nb + 2 * j][d]),
                                 __half2float(ts[nb + 2 * j + 1][d]));
            *(unsigned*)(dst + 2 * j) = v;
        }
    }
}

// ---------------------------------------------------------------------------
// GEMM v4 (unchanged from R9): 128x128 block, 256 threads, warp 32x64,
// K-slab 64, 3-stage cp.async, ldmatrix.x4 fragments. Pitch 144B tiles.
// ---------------------------------------------------------------------------
#define TILE_B 18432                     // 128 rows * 144 B
#define SM_A(st) ((st) * TILE_B)
#define SM_B(st) (3 * TILE_B + (st) * TILE_B)
#define GEMM_SMEM (6 * TILE_B)           // 110592 B

__device__ __forceinline__ void gemm_main(uint32_t sb_, const __half* const arow[4],
                                          const __half* const brow[4],
                                          uint32_t stoff, int lane, int wm, int wn,
                                          float acc[2][8][4]) {
#pragma unroll
    for (int mi = 0; mi < 2; ++mi)
#pragma unroll
        for (int ni = 0; ni < 8; ++ni)
#pragma unroll
            for (int r = 0; r < 4; ++r) acc[mi][ni][r] = 0.0f;

#pragma unroll
    for (int st = 0; st < 2; ++st) {
#pragma unroll
        for (int j = 0; j < 4; ++j) {
            CP_A16(sb_ + SM_A(st) + stoff + j * 32 * 144, arow[j] + st * 64);
            CP_A16(sb_ + SM_B(st) + stoff + j * 32 * 144, brow[j] + st * 64);
        }
        CP_COMMIT();
    }

    const uint32_t a_lm0 = sb_ + (wm + (lane & 15)) * 144 + (lane >> 4) * 16;
    const uint32_t b_lm0 = sb_ + (wn + (lane & 15)) * 144 + (lane >> 4) * 16;

    int cur = 0, nx2 = 2;
    for (int kb = 0; kb < CC / 64; ++kb) {
        if (kb < CC / 64 - 1) { CP_WAIT1(); } else { CP_WAIT0(); }
        __syncthreads();

        if (kb + 2 < CC / 64) {
#pragma unroll
            for (int j = 0; j < 4; ++j) {
                CP_A16(sb_ + SM_A(nx2) + stoff + j * 32 * 144, arow[j] + (kb + 2) * 64);
                CP_A16(sb_ + SM_B(nx2) + stoff + j * 32 * 144, brow[j] + (kb + 2) * 64);
            }
            CP_COMMIT();
        }

        const uint32_t aL = a_lm0 + SM_A(cur);
        const uint32_t bL = b_lm0 + SM_B(cur);
#pragma unroll
        for (int kc = 0; kc < 4; ++kc) {
            unsigned a[2][4], b[4][4];
#pragma unroll
            for (int mi = 0; mi < 2; ++mi)
                ldsm4(a[mi][0], a[mi][1], a[mi][2], a[mi][3],
                      aL + mi * 16 * 144 + kc * 32);
#pragma unroll
            for (int nt = 0; nt < 4; ++nt)
                ldsm4(b[nt][0], b[nt][1], b[nt][2], b[nt][3],
                      bL + nt * 16 * 144 + kc * 32);
#pragma unroll
            for (int mi = 0; mi < 2; ++mi)
#pragma unroll
                for (int nt = 0; nt < 4; ++nt) {
                    mma16(acc[mi][2 * nt], a[mi][0], a[mi][1], a[mi][2], a[mi][3],
                          b[nt][0], b[nt][2]);
                    mma16(acc[mi][2 * nt + 1], a[mi][0], a[mi][1], a[mi][2], a[mi][3],
                          b[nt][1], b[nt][3]);
                }
        }

        cur = (cur == 2) ? 0 : cur + 1;
        nx2 = (nx2 == 2) ? 0 : nx2 + 1;
    }
}

__global__ void __launch_bounds__(256, 2) gemm_qkv_kernel() {
    extern __shared__ char smraw[];
    const uint32_t sb_ = smem_u32(smraw);
    const int tid = threadIdx.x, lane = tid & 31, wid = tid >> 5;
    const int wm = (wid & 3) * 32, wn = (wid >> 2) * 64;
    const int m0 = blockIdx.y * 128, n0 = blockIdx.x * 128;
    const uint32_t stoff = (tid >> 3) * 144 + (tid & 7) * 16;

    const __half* arow[4];
    const __half* brow[4];
#pragma unroll
    for (int j = 0; j < 4; ++j) {
        arow[j] = g_xh + (size_t)(m0 + (tid >> 3) + 32 * j) * CC + (tid & 7) * 8;
        brow[j] = g_wh + (size_t)(n0 + (tid >> 3) + 32 * j) * CC + (tid & 7) * 8;
    }

    float acc[2][8][4];
    gemm_main(sb_, arow, brow, stoff, lane, wm, wn, acc);

#pragma unroll
    for (int mi = 0; mi < 2; ++mi) {
        int mbase = m0 + wm + mi * 16 + (lane >> 2);
#pragma unroll
        for (int ni = 0; ni < 8; ++ni) {
            int n = n0 + wn + ni * 8 + 2 * (lane & 3);
            int sp = n >> 10, rem = n & 1023, h = rem >> 6, d = rem & 63;
            float sc = (sp == 0) ? QSCALE : 1.0f;
#pragma unroll
            for (int rr = 0; rr < 2; ++rr) {
                int m = mbase + rr * 8;
                int b_ = m >> 11, nr = m & 2047;
                unsigned v = pack_h2(acc[mi][ni][rr * 2] * sc, acc[mi][ni][rr * 2 + 1] * sc);
                *(unsigned*)&g_qkvh[((((size_t)sp * BB + b_) * HH + h) * NN + nr) * HD + d] = v;
            }
        }
    }
}

__global__ void __launch_bounds__(256, 2) gemm_proj_kernel(const float* __restrict__ pb,
                                                           float* __restrict__ out) {
    extern __shared__ char smraw[];
    const uint32_t sb_ = smem_u32(smraw);
    const int tid = threadIdx.x, lane = tid & 31, wid = tid >> 5;
    const int wm = (wid & 3) * 32, wn = (wid >> 2) * 64;
    const int m0 = blockIdx.y * 128, n0 = blockIdx.x * 128;
    const uint32_t stoff = (tid >> 3) * 144 + (tid & 7) * 16;

    const __half* arow[4];
    const __half* brow[4];
#pragma unroll
    for (int j = 0; j < 4; ++j) {
        int m = m0 + (tid >> 3) + 32 * j;
        int b_ = m >> 11, nr = m & 2047;
        arow[j] = ((nr < LT) ? (g_xh + ((size_t)b_ * NN + nr) * CC)
                             : (g_xs + ((size_t)b_ * NQ + (nr - LT)) * CC)) + (tid & 7) * 8;
        brow[j] = g_ph + (size_t)(n0 + (tid >> 3) + 32 * j) * CC + (tid & 7) * 8;
    }

    float acc[2][8][4];
    gemm_main(sb_, arow, brow, stoff, lane, wm, wn, acc);

#pragma unroll
    for (int mi = 0; mi < 2; ++mi) {
        int mbase = m0 + wm + mi * 16 + (lane >> 2);
#pragma unroll
        for (int ni = 0; ni < 8; ++ni) {
            int n = n0 + wn + ni * 8 + 2 * (lane & 3);
            float bias0 = pb[n], bias1 = pb[n + 1];
#pragma unroll
            for (int rr = 0; rr < 2; ++rr) {
                int mm = mbase + rr * 8;
                float2 v = make_float2(acc[mi][ni][rr * 2] + bias0,
                                       acc[mi][ni][rr * 2 + 1] + bias1);
                *(float2*)&out[(size_t)mm * CC + n] = v;
            }
        }
    }
}

// ---------------- flash attention v5: BQ=128, 8 warps, per-warp code as R11 --
// smem pitch 144B: Q [128 rows], K [64 rows], Vt [80 rows: 64 V + ones row 64
// (=1.0) + rows 65..79 zero].  18432 + 9216 + 11520 = 39168 B
#define OFF_Q 0
#define OFF_K 18432
#define OFF_V 27648
#define ATT_SMEM 39168

// 64-row tile (256 threads): 512 chunks, 2 per thread
__device__ __forceinline__ void cpa_kv(uint32_t dstB, const __half* src, int pitch, int tid) {
#pragma unroll
    for (int i = 0; i < 2; ++i) {
        int c = tid + 256 * i;
        int row = c >> 3, chh = c & 7;
        CP_A16(dstB + row * 144 + chh * 16, src + (size_t)row * pitch + chh * 8);
    }
}
// 128-row tile (256 threads): 1024 chunks, 4 per thread
__device__ __forceinline__ void cpa_q(uint32_t dstB, const __half* src, int tid) {
#pragma unroll
    for (int i = 0; i < 4; ++i) {
        int c = tid + 256 * i;
        int row = c >> 3, chh = c & 7;
        CP_A16(dstB + row * 144 + chh * 16, src + (size_t)row * HD + chh * 8);
    }
}

__global__ void __launch_bounds__(256, 2) attn_kernel() {
    extern __shared__ char smc[];
    const uint32_t sb = smem_u32(smc);
    const int tid = threadIdx.x, lane = tid & 31, w = tid >> 5;   // w in 0..7
    const int qt = blockIdx.x, h = blockIdx.y, b = blockIdx.z;
    const int bh = b * HH + h;

    const __half* Qb = g_qkvh + (size_t)bh * NN * HD;
    const __half* Kb = g_qkvh + PLANE + (size_t)bh * NN * HD;
    const __half* Vtb = g_vt + (size_t)bh * HD * NN;
    const int q0 = LT + qt * 128;

    cpa_q(sb + OFF_Q, Qb + (size_t)q0 * HD, tid); CP_COMMIT();
    cpa_kv(sb + OFF_K, Kb, HD, tid); CP_COMMIT();
    cpa_kv(sb + OFF_V, Vtb, NN, tid); CP_COMMIT();

    // static ones/zero rows 64..79 of the Vt tile (written once; cpa_kv only
    // ever touches rows 0..63). Row 64 = 1.0h in cols 0..63 -> PV col 64 = l.
    for (int i = tid; i < 16 * 36; i += 256) {
        int row = i / 36, col = i % 36;
        *(unsigned*)(smc + OFF_V + (64 + row) * 144 + col * 4) =
            (row == 0 && col < 32) ? 0x3C003C00u : 0u;
    }

    CP_WAIT2();              // Q resident
    __syncthreads();

    // persistent Q A-fragments (4 k16 chunks over d=64); warp w owns q rows
    // [w*16, w*16+16)
    unsigned qf[4][4];
    {
        const uint32_t qL = sb + OFF_Q + (w * 16 + (lane & 15)) * 144 + (lane >> 4) * 16;
#pragma unroll
        for (int kc = 0; kc < 4; ++kc)
            ldsm4(qf[kc][0], qf[kc][1], qf[kc][2], qf[kc][3], qL + kc * 32);
    }

    float oacc[8][4];
#pragma unroll
    for (int ni = 0; ni < 8; ++ni)
#pragma unroll
        for (int r = 0; r < 4; ++r) oacc[ni][r] = 0.0f;
    float lacc[4] = {0.0f, 0.0f, 0.0f, 0.0f};

    const uint32_t kL = sb + OFF_K + (lane & 15) * 144 + (lane >> 4) * 16;
    const uint32_t vL = sb + OFF_V + (lane & 15) * 144 + (lane >> 4) * 16;

    for (int kt = 0; kt < NT; ++kt) {
        CP_WAIT1();          // K(kt) resident (V(kt) may be in flight)
        __syncthreads();

        // S = Q K^T (log2 domain, scale prefolded into Q)
        float sacc[8][4];
#pragma unroll
        for (int ni = 0; ni < 8; ++ni)
#pragma unroll
            for (int r = 0; r < 4; ++r) sacc[ni][r] = 0.0f;
#pragma unroll
        for (int kc = 0; kc < 4; ++kc) {
            unsigned kb4[4][4];
#pragma unroll
            for (int nt = 0; nt < 4; ++nt)
                ldsm4(kb4[nt][0], kb4[nt][1], kb4[nt][2], kb4[nt][3],
                      kL + nt * 16 * 144 + kc * 32);
#pragma unroll
            for (int nt = 0; nt < 4; ++nt) {
                mma16(sacc[2 * nt], qf[kc][0], qf[kc][1], qf[kc][2], qf[kc][3],
                      kb4[nt][0], kb4[nt][2]);
                mma16(sacc[2 * nt + 1], qf[kc][0], qf[kc][1], qf[kc][2], qf[kc][3],
                      kb4[nt][1], kb4[nt][3]);
            }
        }
        __syncthreads();     // all warps done reading K tile
        if (kt + 1 < NT) {
            cpa_kv(sb + OFF_K, Kb + (size_t)(kt + 1) * 64 * HD, HD, tid);
            CP_COMMIT();
        }

        // softmax: pack logit pairs to half2, one MUFU ex2 per pair; P lands
        // directly in A-fragment layout.
        unsigned pa[4][4];
#pragma unroll
        for (int kc = 0; kc < 4; ++kc) {
            pa[kc][0] = ex2h2(pack_h2(sacc[2 * kc][0], sacc[2 * kc][1]));
            pa[kc][1] = ex2h2(pack_h2(sacc[2 * kc][2], sacc[2 * kc][3]));
            pa[kc][2] = ex2h2(pack_h2(sacc[2 * kc + 1][0], sacc[2 * kc + 1][1]));
            pa[kc][3] = ex2h2(pack_h2(sacc[2 * kc + 1][2], sacc[2 * kc + 1][3]));
        }

        if (kt + 1 < NT) { CP_WAIT1(); } else { CP_WAIT0(); }  // V(kt) resident
        __syncthreads();

        // O += P V ; l += P * ones  (extra B tile rows 64..79)
#pragma unroll
        for (int kc = 0; kc < 4; ++kc) {
            unsigned vb4[4][4], ob[4];
#pragma unroll
            for (int nt = 0; nt < 4; ++nt)
                ldsm4(vb4[nt][0], vb4[nt][1], vb4[nt][2], vb4[nt][3],
                      vL + nt * 16 * 144 + kc * 32);
            ldsm4(ob[0], ob[1], ob[2], ob[3], vL + 4 * 16 * 144 + kc * 32);
#pragma unroll
            for (int nt = 0; nt < 4; ++nt) {
                mma16(oacc[2 * nt], pa[kc][0], pa[kc][1], pa[kc][2], pa[kc][3],
                      vb4[nt][0], vb4[nt][2]);
                mma16(oacc[2 * nt + 1], pa[kc][0], pa[kc][1], pa[kc][2], pa[kc][3],
                      vb4[nt][1], vb4[nt][3]);
            }
            mma16(lacc, pa[kc][0], pa[kc][1], pa[kc][2], pa[kc][3], ob[0], ob[2]);
        }
        __syncthreads();     // all warps done reading V tile
        if (kt + 1 < NT) {
            cpa_kv(sb + OFF_V, Vtb + (size_t)(kt + 1) * 64, NN, tid);
            CP_COMMIT();
        }
    }

    // l sits in col 0 of lacc (lanes with lane&3==0); broadcast across quad.
    const float l0 = __shfl_sync(0xffffffffu, lacc[0], lane & 28);
    const float l1 = __shfl_sync(0xffffffffu, lacc[2], lane & 28);
    const float inv0 = 1.0f / l0, inv1 = 1.0f / l1;

    const int rlo = w * 16 + (lane >> 2), c2 = 2 * (lane & 3);
    const int qrel = qt * 128 + rlo;
#pragma unroll
    for (int ni = 0; ni < 8; ++ni) {
        int d = h * HD + ni * 8 + c2;
        *(unsigned*)&g_xs[((size_t)b * NQ + qrel) * CC + d] =
            pack_h2(oacc[ni][0] * inv0, oacc[ni][1] * inv0);
        *(unsigned*)&g_xs[((size_t)b * NQ + qrel + 8) * CC + d] =
            pack_h2(oacc[ni][2] * inv1, oacc[ni][3] * inv1);
    }
}

// ---------------------------------------------------------------------------
extern "C" void kernel_launch(void* const* d_in, const int* in_sizes, int n_in,
                              void* d_out, int out_size) {
    const float* x     = (const float*)d_in[0];
    const float* qkvw  = (const float*)d_in[1];
    const float* projw = (const float*)d_in[2];
    const float* projb = (const float*)d_in[3];
    float* out = (float*)d_out;
    (void)in_sizes; (void)n_in; (void)out_size;

    cudaFuncSetAttribute(gemm_qkv_kernel, cudaFuncAttributeMaxDynamicSharedMemorySize, GEMM_SMEM);
    cudaFuncSetAttribute(gemm_proj_kernel, cudaFuncAttributeMaxDynamicSharedMemorySize, GEMM_SMEM);
    cudaFuncSetAttribute(attn_kernel, cudaFuncAttributeMaxDynamicSharedMemorySize, ATT_SMEM);

    convert_x_kernel<<<MROWS * CC / (256 * 8), 256>>>(x);
    convert_w_kernel<<<(size_t)N3 * CC / (256 * 8), 256>>>(qkvw, 0);
    convert_w_kernel<<<(size_t)CC * CC / (256 * 8), 256>>>(projw, 1);

    gemm_qkv_kernel<<<dim3(N3 / 128, MROWS / 128), 256, GEMM_SMEM>>>();

    vtrans_kernel<<<dim3(NN / 64, BB * HH), 256>>>();

    attn_kernel<<<dim3(NQ / 128, HH, BB), 256, ATT_SMEM>>>();

    gemm_proj_kernel<<<dim3(CC / 128, MROWS / 128), 256, GEMM_SMEM>>>(projb, out);
}

// round 13
// speedup vs baseline: 1.0259x; 1.0259x over previous
#include <cuda_runtime.h>
#include <cuda_fp16.h>
#include <cstdint>
#include <math.h>

#define BB 4
#define NN 2048
#define CC 1024
#define N3 (3 * CC)
#define HH 16
#define HD 64
#define LT 256
#define NQ (NN - LT)        // 1792
#define MROWS (BB * NN)     // 8192
#define NT (NN / 64)        // 32 K-tiles
#define PLANE ((size_t)BB * HH * NN * HD)

__device__ __half g_qkvh[(size_t)3 * BB * HH * NN * HD];   // q,k,v planes fp16
__device__ __half g_vt[(size_t)BB * HH * HD * NN];         // V transposed [bh][d][n]
__device__ __half g_xs[(size_t)BB * NQ * CC];              // attention out fp16
__device__ __half g_xh[(size_t)MROWS * CC];                // x fp16
__device__ __half g_wh[(size_t)N3 * CC];                   // qkv_w fp16 [n][k]
__device__ __half g_ph[(size_t)CC * CC];                   // proj_w fp16 [n][k]

__device__ __forceinline__ uint32_t smem_u32(const void* p) {
    uint32_t a;
    asm("{ .reg .u64 t; cvta.to.shared.u64 t, %1; cvt.u32.u64 %0, t; }" : "=r"(a) : "l"(p));
    return a;
}
__device__ __forceinline__ void mma16(float* c,
                                      unsigned a0, unsigned a1, unsigned a2, unsigned a3,
                                      unsigned b0, unsigned b1) {
    asm volatile(
        "mma.sync.aligned.m16n8k16.row.col.f32.f16.f16.f32 "
        "{%0,%1,%2,%3},{%4,%5,%6,%7},{%8,%9},{%0,%1,%2,%3};"
        : "+f"(c[0]), "+f"(c[1]), "+f"(c[2]), "+f"(c[3])
        : "r"(a0), "r"(a1), "r"(a2), "r"(a3), "r"(b0), "r"(b1));
}
// fp16-accumulator variant: C/D are 2 b32 regs (4 halves)
__device__ __forceinline__ void mma16h(unsigned* c,
                                       unsigned a0, unsigned a1, unsigned a2, unsigned a3,
                                       unsigned b0, unsigned b1) {
    asm volatile(
        "mma.sync.aligned.m16n8k16.row.col.f16.f16.f16.f16 "
        "{%0,%1},{%2,%3,%4,%5},{%6,%7},{%0,%1};"
        : "+r"(c[0]), "+r"(c[1])
        : "r"(a0), "r"(a1), "r"(a2), "r"(a3), "r"(b0), "r"(b1));
}
__device__ __forceinline__ void ldsm4(unsigned& r0, unsigned& r1, unsigned& r2, unsigned& r3,
                                      uint32_t addr) {
    asm volatile("ldmatrix.sync.aligned.m8n8.x4.shared.b16 {%0,%1,%2,%3}, [%4];"
                 : "=r"(r0), "=r"(r1), "=r"(r2), "=r"(r3) : "r"(addr));
}
__device__ __forceinline__ unsigned pack_h2(float a, float b) {
    __half2 h = __floats2half2_rn(a, b);
    return *(unsigned*)&h;
}
__device__ __forceinline__ unsigned ex2h2(unsigned x) {
    unsigned r;
    asm("ex2.approx.f16x2 %0, %1;" : "=r"(r) : "r"(x));
    return r;
}

#define CP_A16(dst, src) asm volatile("cp.async.cg.shared.global [%0], [%1], 16;" :: "r"(dst), "l"(src))
#define CP_COMMIT()      asm volatile("cp.async.commit_group;" ::: "memory")
#define CP_WAIT0()       asm volatile("cp.async.wait_group 0;" ::: "memory")
#define CP_WAIT1()       asm volatile("cp.async.wait_group 1;" ::: "memory")
#define CP_WAIT2()       asm volatile("cp.async.wait_group 2;" ::: "memory")

// 0.125 * log2(e): folded into Q at QKV epilogue so softmax = ex2(S)
#define QSCALE 0.1803368801111204f

// ---------------- merged fp32 -> fp16 convert (x, qkv_w, proj_w) ----------
#define XU (MROWS * CC / 8)          // 8-half units in x
#define WU (N3 * CC / 8)
#define PU (CC * CC / 8)
__global__ void convert_all_kernel(const float* __restrict__ x,
                                   const float* __restrict__ qw,
                                   const float* __restrict__ pw) {
    size_t u = (size_t)blockIdx.x * 256 + threadIdx.x;
    const float* src;
    __half* dst;
    if (u < XU) {
        src = x; dst = g_xh;
    } else if (u < XU + WU) {
        u -= XU; src = qw; dst = g_wh;
    } else {
        u -= XU + WU; src = pw; dst = g_ph;
    }
    size_t i = u * 8;
    float4 v0 = *(const float4*)(src + i);
    float4 v1 = *(const float4*)(src + i + 4);
    uint4 o;
    o.x = pack_h2(v0.x, v0.y);
    o.y = pack_h2(v0.z, v0.w);
    o.z = pack_h2(v1.x, v1.y);
    o.w = pack_h2(v1.z, v1.w);
    *(uint4*)&dst[i] = o;
}

// ---------------- V plane transpose: [n][d] -> g_vt [d][n] ----------------
__global__ void vtrans_kernel() {
    __shared__ __half ts[64][72];
    const int bx = blockIdx.x, bh = blockIdx.y, tid = threadIdx.x;
    const __half* src = g_qkvh + 2 * PLANE + (size_t)bh * NN * HD + (size_t)bx * 64 * HD;
    {
        int n = tid >> 2, d0 = (tid & 3) * 16;
        *(uint4*)&ts[n][d0] = *(const uint4*)(src + (size_t)n * HD + d0);
        *(uint4*)&ts[n][d0 + 8] = *(const uint4*)(src + (size_t)n * HD + d0 + 8);
    }
    __syncthreads();
    {
        int d = tid >> 2, nb = (tid & 3) * 16;
        __half* dst = g_vt + (size_t)bh * HD * NN + (size_t)d * NN + bx * 64 + nb;
#pragma unroll
        for (int j = 0; j < 8; ++j) {
            unsigned v = pack_h2(__half2float(ts[nb + 2 * j][d]),
                                 __half2float(ts[nb + 2 * j + 1][d]));
            *(unsigned*)(dst + 2 * j) = v;
        }
    }
}

// ---------------------------------------------------------------------------
// GEMM v4 (unchanged from R9): 128x128 block, 256 threads, warp 32x64,
// K-slab 64, 3-stage cp.async, ldmatrix.x4 fragments. Pitch 144B tiles.
// ---------------------------------------------------------------------------
#define TILE_B 18432                     // 128 rows * 144 B
#define SM_A(st) ((st) * TILE_B)
#define SM_B(st) (3 * TILE_B + (st) * TILE_B)
#define GEMM_SMEM (6 * TILE_B)           // 110592 B

__device__ __forceinline__ void gemm_main(uint32_t sb_, const __half* const arow[4],
                                          const __half* const brow[4],
                                          uint32_t stoff, int lane, int wm, int wn,
                                          float acc[2][8][4]) {
#pragma unroll
    for (int mi = 0; mi < 2; ++mi)
#pragma unroll
        for (int ni = 0; ni < 8; ++ni)
#pragma unroll
            for (int r = 0; r < 4; ++r) acc[mi][ni][r] = 0.0f;

#pragma unroll
    for (int st = 0; st < 2; ++st) {
#pragma unroll
        for (int j = 0; j < 4; ++j) {
            CP_A16(sb_ + SM_A(st) + stoff + j * 32 * 144, arow[j] + st * 64);
            CP_A16(sb_ + SM_B(st) + stoff + j * 32 * 144, brow[j] + st * 64);
        }
        CP_COMMIT();
    }

    const uint32_t a_lm0 = sb_ + (wm + (lane & 15)) * 144 + (lane >> 4) * 16;
    const uint32_t b_lm0 = sb_ + (wn + (lane & 15)) * 144 + (lane >> 4) * 16;

    int cur = 0, nx2 = 2;
    for (int kb = 0; kb < CC / 64; ++kb) {
        if (kb < CC / 64 - 1) { CP_WAIT1(); } else { CP_WAIT0(); }
        __syncthreads();

        if (kb + 2 < CC / 64) {
#pragma unroll
            for (int j = 0; j < 4; ++j) {
                CP_A16(sb_ + SM_A(nx2) + stoff + j * 32 * 144, arow[j] + (kb + 2) * 64);
                CP_A16(sb_ + SM_B(nx2) + stoff + j * 32 * 144, brow[j] + (kb + 2) * 64);
            }
            CP_COMMIT();
        }

        const uint32_t aL = a_lm0 + SM_A(cur);
        const uint32_t bL = b_lm0 + SM_B(cur);
#pragma unroll
        for (int kc = 0; kc < 4; ++kc) {
            unsigned a[2][4], b[4][4];
#pragma unroll
            for (int mi = 0; mi < 2; ++mi)
                ldsm4(a[mi][0], a[mi][1], a[mi][2], a[mi][3],
                      aL + mi * 16 * 144 + kc * 32);
#pragma unroll
            for (int nt = 0; nt < 4; ++nt)
                ldsm4(b[nt][0], b[nt][1], b[nt][2], b[nt][3],
                      bL + nt * 16 * 144 + kc * 32);
#pragma unroll
            for (int mi = 0; mi < 2; ++mi)
#pragma unroll
                for (int nt = 0; nt < 4; ++nt) {
                    mma16(acc[mi][2 * nt], a[mi][0], a[mi][1], a[mi][2], a[mi][3],
                          b[nt][0], b[nt][2]);
                    mma16(acc[mi][2 * nt + 1], a[mi][0], a[mi][1], a[mi][2], a[mi][3],
                          b[nt][1], b[nt][3]);
                }
        }

        cur = (cur == 2) ? 0 : cur + 1;
        nx2 = (nx2 == 2) ? 0 : nx2 + 1;
    }
}

__global__ void __launch_bounds__(256, 2) gemm_qkv_kernel() {
    extern __shared__ char smraw[];
    const uint32_t sb_ = smem_u32(smraw);
    const int tid = threadIdx.x, lane = tid & 31, wid = tid >> 5;
    const int wm = (wid & 3) * 32, wn = (wid >> 2) * 64;
    const int m0 = blockIdx.y * 128, n0 = blockIdx.x * 128;
    const uint32_t stoff = (tid >> 3) * 144 + (tid & 7) * 16;

    const __half* arow[4];
    const __half* brow[4];
#pragma unroll
    for (int j = 0; j < 4; ++j) {
        arow[j] = g_xh + (size_t)(m0 + (tid >> 3) + 32 * j) * CC + (tid & 7) * 8;
        brow[j] = g_wh + (size_t)(n0 + (tid >> 3) + 32 * j) * CC + (tid & 7) * 8;
    }

    float acc[2][8][4];
    gemm_main(sb_, arow, brow, stoff, lane, wm, wn, acc);

#pragma unroll
    for (int mi = 0; mi < 2; ++mi) {
        int mbase = m0 + wm + mi * 16 + (lane >> 2);
#pragma unroll
        for (int ni = 0; ni < 8; ++ni) {
            int n = n0 + wn + ni * 8 + 2 * (lane & 3);
            int sp = n >> 10, rem = n & 1023, h = rem >> 6, d = rem & 63;
            float sc = (sp == 0) ? QSCALE : 1.0f;
#pragma unroll
            for (int rr = 0; rr < 2; ++rr) {
                int m = mbase + rr * 8;
                int b_ = m >> 11, nr = m & 2047;
                unsigned v = pack_h2(acc[mi][ni][rr * 2] * sc, acc[mi][ni][rr * 2 + 1] * sc);
                *(unsigned*)&g_qkvh[((((size_t)sp * BB + b_) * HH + h) * NN + nr) * HD + d] = v;
            }
        }
    }
}

__global__ void __launch_bounds__(256, 2) gemm_proj_kernel(const float* __restrict__ pb,
                                                           float* __restrict__ out) {
    extern __shared__ char smraw[];
    const uint32_t sb_ = smem_u32(smraw);
    const int tid = threadIdx.x, lane = tid & 31, wid = tid >> 5;
    const int wm = (wid & 3) * 32, wn = (wid >> 2) * 64;
    const int m0 = blockIdx.y * 128, n0 = blockIdx.x * 128;
    const uint32_t stoff = (tid >> 3) * 144 + (tid & 7) * 16;

    const __half* arow[4];
    const __half* brow[4];
#pragma unroll
    for (int j = 0; j < 4; ++j) {
        int m = m0 + (tid >> 3) + 32 * j;
        int b_ = m >> 11, nr = m & 2047;
        arow[j] = ((nr < LT) ? (g_xh + ((size_t)b_ * NN + nr) * CC)
                             : (g_xs + ((size_t)b_ * NQ + (nr - LT)) * CC)) + (tid & 7) * 8;
        brow[j] = g_ph + (size_t)(n0 + (tid >> 3) + 32 * j) * CC + (tid & 7) * 8;
    }

    float acc[2][8][4];
    gemm_main(sb_, arow, brow, stoff, lane, wm, wn, acc);

#pragma unroll
    for (int mi = 0; mi < 2; ++mi) {
        int mbase = m0 + wm + mi * 16 + (lane >> 2);
#pragma unroll
        for (int ni = 0; ni < 8; ++ni) {
            int n = n0 + wn + ni * 8 + 2 * (lane & 3);
            float bias0 = pb[n], bias1 = pb[n + 1];
#pragma unroll
            for (int rr = 0; rr < 2; ++rr) {
                int mm = mbase + rr * 8;
                float2 v = make_float2(acc[mi][ni][rr * 2] + bias0,
                                       acc[mi][ni][rr * 2 + 1] + bias1);
                *(float2*)&out[(size_t)mm * CC + n] = v;
            }
        }
    }
}

// ---------------- flash attention v6: BQ=64, f16-acc S-MMA ------------------
// smem pitch 144B: Q [64 rows], K [64 rows], Vt [80 rows: 64 V + ones row 64
// (=1.0) + rows 65..79 zero].  9216 + 9216 + 11520 = 29952 B
#define OFF_Q 0
#define OFF_K 9216
#define OFF_V 18432
#define ATT_SMEM 29952

__device__ __forceinline__ void cpa16(uint32_t dstB, const __half* src, int pitch, int tid) {
#pragma unroll
    for (int i = 0; i < 4; ++i) {
        int c = tid + 128 * i;
        int row = c >> 3, chh = c & 7;
        CP_A16(dstB + row * 144 + chh * 16, src + (size_t)row * pitch + chh * 8);
    }
}

__global__ void __launch_bounds__(128, 4) attn_kernel() {
    extern __shared__ char smc[];
    const uint32_t sb = smem_u32(smc);
    const int tid = threadIdx.x, lane = tid & 31, w = tid >> 5;
    const int qt = blockIdx.x, h = blockIdx.y, b = blockIdx.z;
    const int bh = b * HH + h;

    const __half* Qb = g_qkvh + (size_t)bh * NN * HD;
    const __half* Kb = g_qkvh + PLANE + (size_t)bh * NN * HD;
    const __half* Vtb = g_vt + (size_t)bh * HD * NN;
    const int q0 = LT + qt * 64;

    cpa16(sb + OFF_Q, Qb + (size_t)q0 * HD, HD, tid); CP_COMMIT();
    cpa16(sb + OFF_K, Kb, HD, tid); CP_COMMIT();
    cpa16(sb + OFF_V, Vtb, NN, tid); CP_COMMIT();

    // static ones/zero rows 64..79 of the Vt tile (written once; cpa16 only
    // ever touches rows 0..63). Row 64 = 1.0h in cols 0..63 -> PV col 64 = l.
    for (int i = tid; i < 16 * 36; i += 128) {
        int row = i / 36, col = i % 36;
        *(unsigned*)(smc + OFF_V + (64 + row) * 144 + col * 4) =
            (row == 0 && col < 32) ? 0x3C003C00u : 0u;
    }

    CP_WAIT2();              // Q resident
    __syncthreads();

    // persistent Q A-fragments (4 k16 chunks over d=64)
    unsigned qf[4][4];
    {
        const uint32_t qL = sb + OFF_Q + (w * 16 + (lane & 15)) * 144 + (lane >> 4) * 16;
#pragma unroll
        for (int kc = 0; kc < 4; ++kc)
            ldsm4(qf[kc][0], qf[kc][1], qf[kc][2], qf[kc][3], qL + kc * 32);
    }

    float oacc[8][4];
#pragma unroll
    for (int ni = 0; ni < 8; ++ni)
#pragma unroll
        for (int r = 0; r < 4; ++r) oacc[ni][r] = 0.0f;
    float lacc[4] = {0.0f, 0.0f, 0.0f, 0.0f};

    const uint32_t kL = sb + OFF_K + (lane & 15) * 144 + (lane >> 4) * 16;
    const uint32_t vL = sb + OFF_V + (lane & 15) * 144 + (lane >> 4) * 16;

    for (int kt = 0; kt < NT; ++kt) {
        CP_WAIT1();          // K(kt) resident (V(kt) may be in flight)
        __syncthreads();

        // S = Q K^T, fp16 accumulators (2 packed regs per 8-col block).
        // C layout: c[0] = {(r,2t),(r,2t+1)}, c[1] = {(r+8,2t),(r+8,2t+1)}
        unsigned sacch[8][2];
#pragma unroll
        for (int ni = 0; ni < 8; ++ni) { sacch[ni][0] = 0u; sacch[ni][1] = 0u; }
#pragma unroll
        for (int kc = 0; kc < 4; ++kc) {
            unsigned kb4[4][4];
#pragma unroll
            for (int nt = 0; nt < 4; ++nt)
                ldsm4(kb4[nt][0], kb4[nt][1], kb4[nt][2], kb4[nt][3],
                      kL + nt * 16 * 144 + kc * 32);
#pragma unroll
            for (int nt = 0; nt < 4; ++nt) {
                mma16h(sacch[2 * nt], qf[kc][0], qf[kc][1], qf[kc][2], qf[kc][3],
                       kb4[nt][0], kb4[nt][2]);
                mma16h(sacch[2 * nt + 1], qf[kc][0], qf[kc][1], qf[kc][2], qf[kc][3],
                       kb4[nt][1], kb4[nt][3]);
            }
        }
        __syncthreads();     // all warps done reading K tile
        if (kt + 1 < NT) {
            cpa16(sb + OFF_K, Kb + (size_t)(kt + 1) * 64 * HD, HD, tid);
            CP_COMMIT();
        }

        // softmax: sacch pairs ARE the A-fragment half2 pairs; one ex2 each.
        // pa[kc][0]=(r,16kc+2t) pa[kc][1]=(r+8,..) pa[kc][2]=(r,16kc+8+2t) pa[kc][3]=(r+8,..)
        unsigned pa[4][4];
#pragma unroll
        for (int kc = 0; kc < 4; ++kc) {
            pa[kc][0] = ex2h2(sacch[2 * kc][0]);
            pa[kc][1] = ex2h2(sacch[2 * kc][1]);
            pa[kc][2] = ex2h2(sacch[2 * kc + 1][0]);
            pa[kc][3] = ex2h2(sacch[2 * kc + 1][1]);
        }

        if (kt + 1 < NT) { CP_WAIT1(); } else { CP_WAIT0(); }  // V(kt) resident
        __syncthreads();

        // O += P V ; l += P * ones  (extra B tile rows 64..79), fp32 acc
#pragma unroll
        for (int kc = 0; kc < 4; ++kc) {
            unsigned vb4[4][4], ob[4];
#pragma unroll
            for (int nt = 0; nt < 4; ++nt)
                ldsm4(vb4[nt][0], vb4[nt][1], vb4[nt][2], vb4[nt][3],
                      vL + nt * 16 * 144 + kc * 32);
            ldsm4(ob[0], ob[1], ob[2], ob[3], vL + 4 * 16 * 144 + kc * 32);
#pragma unroll
            for (int nt = 0; nt < 4; ++nt) {
                mma16(oacc[2 * nt], pa[kc][0], pa[kc][1], pa[kc][2], pa[kc][3],
                      vb4[nt][0], vb4[nt][2]);
                mma16(oacc[2 * nt + 1], pa[kc][0], pa[kc][1], pa[kc][2], pa[kc][3],
                      vb4[nt][1], vb4[nt][3]);
            }
            mma16(lacc, pa[kc][0], pa[kc][1], pa[kc][2], pa[kc][3], ob[0], ob[2]);
        }
        __syncthreads();     // all warps done reading V tile
        if (kt + 1 < NT) {
            cpa16(sb + OFF_V, Vtb + (size_t)(kt + 1) * 64, NN, tid);
            CP_COMMIT();
        }
    }

    // l sits in col 0 of lacc (lanes with lane&3==0); broadcast across quad.
    const float l0 = __shfl_sync(0xffffffffu, lacc[0], lane & 28);
    const float l1 = __shfl_sync(0xffffffffu, lacc[2], lane & 28);
    const float inv0 = 1.0f / l0, inv1 = 1.0f / l1;

    const int rlo = w * 16 + (lane >> 2), c2 = 2 * (lane & 3);
    const int qrel = qt * 64 + rlo;
#pragma unroll
    for (int ni = 0; ni < 8; ++ni) {
        int d = h * HD + ni * 8 + c2;
        *(unsigned*)&g_xs[((size_t)b * NQ + qrel) * CC + d] =
            pack_h2(oacc[ni][0] * inv0, oacc[ni][1] * inv0);
        *(unsigned*)&g_xs[((size_t)b * NQ + qrel + 8) * CC + d] =
            pack_h2(oacc[ni][2] * inv1, oacc[ni][3] * inv1);
    }
}

// ---------------------------------------------------------------------------
extern "C" void kernel_launch(void* const* d_in, const int* in_sizes, int n_in,
                              void* d_out, int out_size) {
    const float* x     = (const float*)d_in[0];
    const float* qkvw  = (const float*)d_in[1];
    const float* projw = (const float*)d_in[2];
    const float* projb = (const float*)d_in[3];
    float* out = (float*)d_out;
    (void)in_sizes; (void)n_in; (void)out_size;

    cudaFuncSetAttribute(gemm_qkv_kernel, cudaFuncAttributeMaxDynamicSharedMemorySize, GEMM_SMEM);
    cudaFuncSetAttribute(gemm_proj_kernel, cudaFuncAttributeMaxDynamicSharedMemorySize, GEMM_SMEM);
    cudaFuncSetAttribute(attn_kernel, cudaFuncAttributeMaxDynamicSharedMemorySize, ATT_SMEM);

    convert_all_kernel<<<(XU + WU + PU) / 256, 256>>>(x, qkvw, projw);

    gemm_qkv_kernel<<<dim3(N3 / 128, MROWS / 128), 256, GEMM_SMEM>>>();

    vtrans_kernel<<<dim3(NN / 64, BB * HH), 256>>>();

    attn_kernel<<<dim3(NQ / 64, HH, BB), 128, ATT_SMEM>>>();

    gemm_proj_kernel<<<dim3(CC / 128, MROWS / 128), 256, GEMM_SMEM>>>(projb, out);
}

// round 14
// speedup vs baseline: 1.1025x; 1.0747x over previous
#include <cuda_runtime.h>
#include <cuda_fp16.h>
#include <cstdint>
#include <math.h>

#define BB 4
#define NN 2048
#define CC 1024
#define N3 (3 * CC)
#define HH 16
#define HD 64
#define LT 256
#define NQ (NN - LT)        // 1792
#define MROWS (BB * NN)     // 8192
#define NT (NN / 64)        // 32 K-tiles
#define PLANE ((size_t)BB * HH * NN * HD)

__device__ __half g_qkvh[(size_t)3 * BB * HH * NN * HD];   // q,k,v planes fp16
__device__ __half g_xs[(size_t)BB * NQ * CC];              // attention out fp16
__device__ __half g_xh[(size_t)MROWS * CC];                // x fp16
__device__ __half g_wh[(size_t)N3 * CC];                   // qkv_w fp16 [n][k]
__device__ __half g_ph[(size_t)CC * CC];                   // proj_w fp16 [n][k]

__device__ __forceinline__ uint32_t smem_u32(const void* p) {
    uint32_t a;
    asm("{ .reg .u64 t; cvta.to.shared.u64 t, %1; cvt.u32.u64 %0, t; }" : "=r"(a) : "l"(p));
    return a;
}
__device__ __forceinline__ void mma16(float* c,
                                      unsigned a0, unsigned a1, unsigned a2, unsigned a3,
                                      unsigned b0, unsigned b1) {
    asm volatile(
        "mma.sync.aligned.m16n8k16.row.col.f32.f16.f16.f32 "
        "{%0,%1,%2,%3},{%4,%5,%6,%7},{%8,%9},{%0,%1,%2,%3};"
        : "+f"(c[0]), "+f"(c[1]), "+f"(c[2]), "+f"(c[3])
        : "r"(a0), "r"(a1), "r"(a2), "r"(a3), "r"(b0), "r"(b1));
}
// fp16-accumulator variant: C/D are 2 b32 regs (4 halves)
__device__ __forceinline__ void mma16h(unsigned* c,
                                       unsigned a0, unsigned a1, unsigned a2, unsigned a3,
                                       unsigned b0, unsigned b1) {
    asm volatile(
        "mma.sync.aligned.m16n8k16.row.col.f16.f16.f16.f16 "
        "{%0,%1},{%2,%3,%4,%5},{%6,%7},{%0,%1};"
        : "+r"(c[0]), "+r"(c[1])
        : "r"(a0), "r"(a1), "r"(a2), "r"(a3), "r"(b0), "r"(b1));
}
__device__ __forceinline__ void ldsm4(unsigned& r0, unsigned& r1, unsigned& r2, unsigned& r3,
                                      uint32_t addr) {
    asm volatile("ldmatrix.sync.aligned.m8n8.x4.shared.b16 {%0,%1,%2,%3}, [%4];"
                 : "=r"(r0), "=r"(r1), "=r"(r2), "=r"(r3) : "r"(addr));
}
__device__ __forceinline__ void ldsm4t(unsigned& r0, unsigned& r1, unsigned& r2, unsigned& r3,
                                       uint32_t addr) {
    asm volatile("ldmatrix.sync.aligned.m8n8.x4.trans.shared.b16 {%0,%1,%2,%3}, [%4];"
                 : "=r"(r0), "=r"(r1), "=r"(r2), "=r"(r3) : "r"(addr));
}
__device__ __forceinline__ void ldsm2t(unsigned& r0, unsigned& r1, uint32_t addr) {
    asm volatile("ldmatrix.sync.aligned.m8n8.x2.trans.shared.b16 {%0,%1}, [%2];"
                 : "=r"(r0), "=r"(r1) : "r"(addr));
}
__device__ __forceinline__ unsigned pack_h2(float a, float b) {
    __half2 h = __floats2half2_rn(a, b);
    return *(unsigned*)&h;
}
__device__ __forceinline__ unsigned ex2h2(unsigned x) {
    unsigned r;
    asm("ex2.approx.f16x2 %0, %1;" : "=r"(r) : "r"(x));
    return r;
}

#define CP_A16(dst, src) asm volatile("cp.async.cg.shared.global [%0], [%1], 16;" :: "r"(dst), "l"(src))
#define CP_COMMIT()      asm volatile("cp.async.commit_group;" ::: "memory")
#define CP_WAIT0()       asm volatile("cp.async.wait_group 0;" ::: "memory")
#define CP_WAIT1()       asm volatile("cp.async.wait_group 1;" ::: "memory")
#define CP_WAIT2()       asm volatile("cp.async.wait_group 2;" ::: "memory")

// 0.125 * log2(e): folded into Q at QKV epilogue so softmax = ex2(S)
#define QSCALE 0.1803368801111204f

// ---------------- merged fp32 -> fp16 convert (x, qkv_w, proj_w) ----------
#define XU (MROWS * CC / 8)          // 8-half units in x
#define WU (N3 * CC / 8)
#define PU (CC * CC / 8)
__global__ void convert_all_kernel(const float* __restrict__ x,
                                   const float* __restrict__ qw,
                                   const float* __restrict__ pw) {
    size_t u = (size_t)blockIdx.x * 256 + threadIdx.x;
    const float* src;
    __half* dst;
    if (u < XU) {
        src = x; dst = g_xh;
    } else if (u < XU + WU) {
        u -= XU; src = qw; dst = g_wh;
    } else {
        u -= XU + WU; src = pw; dst = g_ph;
    }
    size_t i = u * 8;
    float4 v0 = *(const float4*)(src + i);
    float4 v1 = *(const float4*)(src + i + 4);
    uint4 o;
    o.x = pack_h2(v0.x, v0.y);
    o.y = pack_h2(v0.z, v0.w);
    o.z = pack_h2(v1.x, v1.y);
    o.w = pack_h2(v1.z, v1.w);
    *(uint4*)&dst[i] = o;
}

// ---------------------------------------------------------------------------
// GEMM v4 (unchanged from R9): 128x128 block, 256 threads, warp 32x64,
// K-slab 64, 3-stage cp.async, ldmatrix.x4 fragments. Pitch 144B tiles.
// ---------------------------------------------------------------------------
#define TILE_B 18432                     // 128 rows * 144 B
#define SM_A(st) ((st) * TILE_B)
#define SM_B(st) (3 * TILE_B + (st) * TILE_B)
#define GEMM_SMEM (6 * TILE_B)           // 110592 B

__device__ __forceinline__ void gemm_main(uint32_t sb_, const __half* const arow[4],
                                          const __half* const brow[4],
                                          uint32_t stoff, int lane, int wm, int wn,
                                          float acc[2][8][4]) {
#pragma unroll
    for (int mi = 0; mi < 2; ++mi)
#pragma unroll
        for (int ni = 0; ni < 8; ++ni)
#pragma unroll
            for (int r = 0; r < 4; ++r) acc[mi][ni][r] = 0.0f;

#pragma unroll
    for (int st = 0; st < 2; ++st) {
#pragma unroll
        for (int j = 0; j < 4; ++j) {
            CP_A16(sb_ + SM_A(st) + stoff + j * 32 * 144, arow[j] + st * 64);
            CP_A16(sb_ + SM_B(st) + stoff + j * 32 * 144, brow[j] + st * 64);
        }
        CP_COMMIT();
    }

    const uint32_t a_lm0 = sb_ + (wm + (lane & 15)) * 144 + (lane >> 4) * 16;
    const uint32_t b_lm0 = sb_ + (wn + (lane & 15)) * 144 + (lane >> 4) * 16;

    int cur = 0, nx2 = 2;
    for (int kb = 0; kb < CC / 64; ++kb) {
        if (kb < CC / 64 - 1) { CP_WAIT1(); } else { CP_WAIT0(); }
        __syncthreads();

        if (kb + 2 < CC / 64) {
#pragma unroll
            for (int j = 0; j < 4; ++j) {
                CP_A16(sb_ + SM_A(nx2) + stoff + j * 32 * 144, arow[j] + (kb + 2) * 64);
                CP_A16(sb_ + SM_B(nx2) + stoff + j * 32 * 144, brow[j] + (kb + 2) * 64);
            }
            CP_COMMIT();
        }

        const uint32_t aL = a_lm0 + SM_A(cur);
        const uint32_t bL = b_lm0 + SM_B(cur);
#pragma unroll
        for (int kc = 0; kc < 4; ++kc) {
            unsigned a[2][4], b[4][4];
#pragma unroll
            for (int mi = 0; mi < 2; ++mi)
                ldsm4(a[mi][0], a[mi][1], a[mi][2], a[mi][3],
                      aL + mi * 16 * 144 + kc * 32);
#pragma unroll
            for (int nt = 0; nt < 4; ++nt)
                ldsm4(b[nt][0], b[nt][1], b[nt][2], b[nt][3],
                      bL + nt * 16 * 144 + kc * 32);
#pragma unroll
            for (int mi = 0; mi < 2; ++mi)
#pragma unroll
                for (int nt = 0; nt < 4; ++nt) {
                    mma16(acc[mi][2 * nt], a[mi][0], a[mi][1], a[mi][2], a[mi][3],
                          b[nt][0], b[nt][2]);
                    mma16(acc[mi][2 * nt + 1], a[mi][0], a[mi][1], a[mi][2], a[mi][3],
                          b[nt][1], b[nt][3]);
                }
        }

        cur = (cur == 2) ? 0 : cur + 1;
        nx2 = (nx2 == 2) ? 0 : nx2 + 1;
    }
}

__global__ void __launch_bounds__(256, 2) gemm_qkv_kernel() {
    const int m0 = blockIdx.y * 128, n0 = blockIdx.x * 128;
    // dead-tile skip: q-plane rows nr < LT are never consumed by attention
    if (n0 < CC && (m0 & (NN - 1)) < LT) return;

    extern __shared__ char smraw[];
    const uint32_t sb_ = smem_u32(smraw);
    const int tid = threadIdx.x, lane = tid & 31, wid = tid >> 5;
    const int wm = (wid & 3) * 32, wn = (wid >> 2) * 64;
    const uint32_t stoff = (tid >> 3) * 144 + (tid & 7) * 16;

    const __half* arow[4];
    const __half* brow[4];
#pragma unroll
    for (int j = 0; j < 4; ++j) {
        arow[j] = g_xh + (size_t)(m0 + (tid >> 3) + 32 * j) * CC + (tid & 7) * 8;
        brow[j] = g_wh + (size_t)(n0 + (tid >> 3) + 32 * j) * CC + (tid & 7) * 8;
    }

    float acc[2][8][4];
    gemm_main(sb_, arow, brow, stoff, lane, wm, wn, acc);

#pragma unroll
    for (int mi = 0; mi < 2; ++mi) {
        int mbase = m0 + wm + mi * 16 + (lane >> 2);
#pragma unroll
        for (int ni = 0; ni < 8; ++ni) {
            int n = n0 + wn + ni * 8 + 2 * (lane & 3);
            int sp = n >> 10, rem = n & 1023, h = rem >> 6, d = rem & 63;
            float sc = (sp == 0) ? QSCALE : 1.0f;
#pragma unroll
            for (int rr = 0; rr < 2; ++rr) {
                int m = mbase + rr * 8;
                int b_ = m >> 11, nr = m & 2047;
                unsigned v = pack_h2(acc[mi][ni][rr * 2] * sc, acc[mi][ni][rr * 2 + 1] * sc);
                *(unsigned*)&g_qkvh[((((size_t)sp * BB + b_) * HH + h) * NN + nr) * HD + d] = v;
            }
        }
    }
}

__global__ void __launch_bounds__(256, 2) gemm_proj_kernel(const float* __restrict__ pb,
                                                           float* __restrict__ out) {
    extern __shared__ char smraw[];
    const uint32_t sb_ = smem_u32(smraw);
    const int tid = threadIdx.x, lane = tid & 31, wid = tid >> 5;
    const int wm = (wid & 3) * 32, wn = (wid >> 2) * 64;
    const int m0 = blockIdx.y * 128, n0 = blockIdx.x * 128;
    const uint32_t stoff = (tid >> 3) * 144 + (tid & 7) * 16;

    const __half* arow[4];
    const __half* brow[4];
#pragma unroll
    for (int j = 0; j < 4; ++j) {
        int m = m0 + (tid >> 3) + 32 * j;
        int b_ = m >> 11, nr = m & 2047;
        arow[j] = ((nr < LT) ? (g_xh + ((size_t)b_ * NN + nr) * CC)
                             : (g_xs + ((size_t)b_ * NQ + (nr - LT)) * CC)) + (tid & 7) * 8;
        brow[j] = g_ph + (size_t)(n0 + (tid >> 3) + 32 * j) * CC + (tid & 7) * 8;
    }

    float acc[2][8][4];
    gemm_main(sb_, arow, brow, stoff, lane, wm, wn, acc);

#pragma unroll
    for (int mi = 0; mi < 2; ++mi) {
        int mbase = m0 + wm + mi * 16 + (lane >> 2);
#pragma unroll
        for (int ni = 0; ni < 8; ++ni) {
            int n = n0 + wn + ni * 8 + 2 * (lane & 3);
            float bias0 = pb[n], bias1 = pb[n + 1];
#pragma unroll
            for (int rr = 0; rr < 2; ++rr) {
                int mm = mbase + rr * 8;
                float2 v = make_float2(acc[mi][ni][rr * 2] + bias0,
                                       acc[mi][ni][rr * 2 + 1] + bias1);
                *(float2*)&out[(size_t)mm * CC + n] = v;
            }
        }
    }
}

// ---------------- flash attention v7: trans-ldmatrix V, no vtrans ----------
// smem pitch 144B: Q [64 rows], K [64 rows], V [64 rows, natural [n][d]].
// V cols 64..71 of every row are STATIC {1,0,...}: cp.async writes only
// bytes 0..127, so the ones column survives the whole loop -> l = P @ ones.
#define OFF_Q 0
#define OFF_K 9216
#define OFF_V 18432
#define ATT_SMEM 27648

__device__ __forceinline__ void cpa16(uint32_t dstB, const __half* src, int pitch, int tid) {
#pragma unroll
    for (int i = 0; i < 4; ++i) {
        int c = tid + 128 * i;
        int row = c >> 3, chh = c & 7;
        CP_A16(dstB + row * 144 + chh * 16, src + (size_t)row * pitch + chh * 8);
    }
}

__global__ void __launch_bounds__(128, 4) attn_kernel() {
    extern __shared__ char smc[];
    const uint32_t sb = smem_u32(smc);
    const int tid = threadIdx.x, lane = tid & 31, w = tid >> 5;
    const int qt = blockIdx.x, h = blockIdx.y, b = blockIdx.z;
    const int bh = b * HH + h;

    const __half* Qb = g_qkvh + (size_t)bh * NN * HD;
    const __half* Kb = g_qkvh + PLANE + (size_t)bh * NN * HD;
    const __half* Vb = g_qkvh + 2 * PLANE + (size_t)bh * NN * HD;
    const int q0 = LT + qt * 64;

    cpa16(sb + OFF_Q, Qb + (size_t)q0 * HD, HD, tid); CP_COMMIT();
    cpa16(sb + OFF_K, Kb, HD, tid); CP_COMMIT();
    cpa16(sb + OFF_V, Vb, HD, tid); CP_COMMIT();

    // static ones column: bytes 128..143 of each V row = {1.0h, 0 x7}
    if (tid < 64) {
        uint4 z = make_uint4(0x00003C00u, 0u, 0u, 0u);
        *(uint4*)(smc + OFF_V + tid * 144 + 128) = z;
    }

    CP_WAIT2();              // Q resident
    __syncthreads();

    // persistent Q A-fragments (4 k16 chunks over d=64)
    unsigned qf[4][4];
    {
        const uint32_t qL = sb + OFF_Q + (w * 16 + (lane & 15)) * 144 + (lane >> 4) * 16;
#pragma unroll
        for (int kc = 0; kc < 4; ++kc)
            ldsm4(qf[kc][0], qf[kc][1], qf[kc][2], qf[kc][3], qL + kc * 32);
    }

    float oacc[8][4];
#pragma unroll
    for (int ni = 0; ni < 8; ++ni)
#pragma unroll
        for (int r = 0; r < 4; ++r) oacc[ni][r] = 0.0f;
    float lacc[4] = {0.0f, 0.0f, 0.0f, 0.0f};

    const uint32_t kL = sb + OFF_K + (lane & 15) * 144 + (lane >> 4) * 16;
    // trans B-frag addressing: lanes 0-7 -> n row (lane&7), d-chunk lo;
    // 8-15 -> same rows, d-chunk hi; 16-23 -> n rows +8, lo; 24-31 -> hi.
    const uint32_t vtrL = sb + OFF_V + ((lane & 7) + ((lane >> 4) & 1) * 8) * 144
                                     + ((lane >> 3) & 1) * 16;
    const uint32_t oneL = sb + OFF_V + (lane & 15) * 144 + 128;

    for (int kt = 0; kt < NT; ++kt) {
        CP_WAIT1();          // K(kt) resident (V(kt) may be in flight)
        __syncthreads();

        // S = Q K^T, fp16 accumulators
        unsigned sacch[8][2];
#pragma unroll
        for (int ni = 0; ni < 8; ++ni) { sacch[ni][0] = 0u; sacch[ni][1] = 0u; }
#pragma unroll
        for (int kc = 0; kc < 4; ++kc) {
            unsigned kb4[4][4];
#pragma unroll
            for (int nt = 0; nt < 4; ++nt)
                ldsm4(kb4[nt][0], kb4[nt][1], kb4[nt][2], kb4[nt][3],
                      kL + nt * 16 * 144 + kc * 32);
#pragma unroll
            for (int nt = 0; nt < 4; ++nt) {
                mma16h(sacch[2 * nt], qf[kc][0], qf[kc][1], qf[kc][2], qf[kc][3],
                       kb4[nt][0], kb4[nt][2]);
                mma16h(sacch[2 * nt + 1], qf[kc][0], qf[kc][1], qf[kc][2], qf[kc][3],
                       kb4[nt][1], kb4[nt][3]);
            }
        }
        __syncthreads();     // all warps done reading K tile
        if (kt + 1 < NT) {
            cpa16(sb + OFF_K, Kb + (size_t)(kt + 1) * 64 * HD, HD, tid);
            CP_COMMIT();
        }

        // softmax: sacch pairs ARE the A-fragment half2 pairs; one ex2 each
        unsigned pa[4][4];
#pragma unroll
        for (int kc = 0; kc < 4; ++kc) {
            pa[kc][0] = ex2h2(sacch[2 * kc][0]);
            pa[kc][1] = ex2h2(sacch[2 * kc][1]);
            pa[kc][2] = ex2h2(sacch[2 * kc + 1][0]);
            pa[kc][3] = ex2h2(sacch[2 * kc + 1][1]);
        }

        if (kt + 1 < NT) { CP_WAIT1(); } else { CP_WAIT0(); }  // V(kt) resident
        __syncthreads();

        // O += P V (B-frags via ldmatrix.trans from natural V [n][d]);
        // l += P @ ones (static col 64)
#pragma unroll
        for (int kc = 0; kc < 4; ++kc) {
            unsigned tr[4][4], ob2[2];
#pragma unroll
            for (int nt = 0; nt < 4; ++nt)
                ldsm4t(tr[nt][0], tr[nt][1], tr[nt][2], tr[nt][3],
                       vtrL + kc * 2304 + nt * 32);
            ldsm2t(ob2[0], ob2[1], oneL + kc * 2304);
#pragma unroll
            for (int nt = 0; nt < 4; ++nt) {
                mma16(oacc[2 * nt], pa[kc][0], pa[kc][1], pa[kc][2], pa[kc][3],
                      tr[nt][0], tr[nt][2]);
                mma16(oacc[2 * nt + 1], pa[kc][0], pa[kc][1], pa[kc][2], pa[kc][3],
                      tr[nt][1], tr[nt][3]);
            }
            mma16(lacc, pa[kc][0], pa[kc][1], pa[kc][2], pa[kc][3], ob2[0], ob2[1]);
        }
        __syncthreads();     // all warps done reading V tile
        if (kt + 1 < NT) {
            cpa16(sb + OFF_V, Vb + (size_t)(kt + 1) * 64 * HD, HD, tid);
            CP_COMMIT();
        }
    }

    // l sits in col 0 of lacc (lanes with lane&3==0); broadcast across quad.
    const float l0 = __shfl_sync(0xffffffffu, lacc[0], lane & 28);
    const float l1 = __shfl_sync(0xffffffffu, lacc[2], lane & 28);
    const float inv0 = 1.0f / l0, inv1 = 1.0f / l1;

    const int rlo = w * 16 + (lane >> 2), c2 = 2 * (lane & 3);
    const int qrel = qt * 64 + rlo;
#pragma unroll
    for (int ni = 0; ni < 8; ++ni) {
        int d = h * HD + ni * 8 + c2;
        *(unsigned*)&g_xs[((size_t)b * NQ + qrel) * CC + d] =
            pack_h2(oacc[ni][0] * inv0, oacc[ni][1] * inv0);
        *(unsigned*)&g_xs[((size_t)b * NQ + qrel + 8) * CC + d] =
            pack_h2(oacc[ni][2] * inv1, oacc[ni][3] * inv1);
    }
}

// ---------------------------------------------------------------------------
extern "C" void kernel_launch(void* const* d_in, const int* in_sizes, int n_in,
                              void* d_out, int out_size) {
    const float* x     = (const float*)d_in[0];
    const float* qkvw  = (const float*)d_in[1];
    const float* projw = (const float*)d_in[2];
    const float* projb = (const float*)d_in[3];
    float* out = (float*)d_out;
    (void)in_sizes; (void)n_in; (void)out_size;

    cudaFuncSetAttribute(gemm_qkv_kernel, cudaFuncAttributeMaxDynamicSharedMemorySize, GEMM_SMEM);
    cudaFuncSetAttribute(gemm_proj_kernel, cudaFuncAttributeMaxDynamicSharedMemorySize, GEMM_SMEM);
    cudaFuncSetAttribute(attn_kernel, cudaFuncAttributeMaxDynamicSharedMemorySize, ATT_SMEM);

    convert_all_kernel<<<(XU + WU + PU) / 256, 256>>>(x, qkvw, projw);

    gemm_qkv_kernel<<<dim3(N3 / 128, MROWS / 128), 256, GEMM_SMEM>>>();

    attn_kernel<<<dim3(NQ / 64, HH, BB), 128, ATT_SMEM>>>();

    gemm_proj_kernel<<<dim3(CC / 128, MROWS / 128), 256, GEMM_SMEM>>>(projb, out);
}